// round 1
// baseline (speedup 1.0000x reference)
#include <cuda_runtime.h>
#include <math.h>

#define Dm   512
#define Hn   8
#define DHn  64
#define Tn   1024
#define NT   2048      // B*T tokens
#define Ln   4
#define En   8
#define FFn  2048
#define NEn  4096      // token-slots (NT * top-k)

// ------------------------- scratch (device globals, no allocs) ---------------
__device__ __align__(128) float g_y[NT * Dm];
__device__ __align__(128) float g_qkv[3 * NT * Dm];
__device__ __align__(128) float g_attn[NT * Dm];
__device__ __align__(128) float g_proj[NT * Dm];
__device__ __align__(128) float g_probs[NT * En];
__device__ __align__(128) float g_gates[NEn];
__device__ __align__(128) float g_H[(size_t)NEn * FFn];     // 32 MB expert hidden
__device__ __align__(128) float g_eout[(size_t)NEn * Dm];   // per-(token,slot) expert out
__device__ int g_topi[NEn];
__device__ int g_perm[NEn];
__device__ int g_offs[En + 1];

// ------------------------- embedding ----------------------------------------
__global__ void embed_k(const int* __restrict__ ids, const float* __restrict__ emb,
                        const float* __restrict__ pos, float* __restrict__ y)
{
    int t = blockIdx.x;
    int id = ids[t];
    int tq = t & (Tn - 1);
    const float* er = emb + (long)id * Dm;
    const float* pr = pos + (long)tq * Dm;
    float* yr = y + (long)t * Dm;
    for (int d = threadIdx.x; d < Dm; d += blockDim.x)
        yr[d] = er[d] + pr[d];
}

// ------------------------- generic tiled SGEMM ------------------------------
// C[M,N] = A[M,K] @ B[K,N], row-major. 128x64x16 tiles, 256 threads, 8x4 micro.
constexpr int BM = 128, BN = 64, BK = 16;

struct RowA {
    const float* A; int lda; long zstride; int M;
    __device__ int setz(int z) { A += (long)z * zstride; return M; }
    __device__ const float* row(int m) const { return A + (long)m * lda; }
};
struct GatherA {
    const float* X; const int* perm; const int* offs; int base;
    __device__ int setz(int e) { base = offs[e]; return offs[e + 1] - base; }
    __device__ const float* row(int m) const { return X + (long)(perm[base + m] >> 1) * Dm; }
};
struct HRowA {
    const float* Hb; const int* offs; const float* A;
    __device__ int setz(int e) { int b0 = offs[e]; A = Hb + (long)b0 * FFn; return offs[e + 1] - b0; }
    __device__ const float* row(int m) const { return A + (long)m * FFn; }
};

template <bool RELU>
struct EpiBias {
    const float* bias; long biasZ; float* C; long cZ; int ldc;
    __device__ void setz(int z) { bias += (long)z * biasZ; C += (long)z * cZ; }
    __device__ void op(int m, int n, float v) {
        v += bias[n];
        if (RELU) v = fmaxf(v, 0.f);
        C[(long)m * ldc + n] = v;
    }
};
struct EpiMoE1 {  // relu(acc + b1) -> H rows at expert base
    const float* b1l; const int* offs; float* Hb;
    const float* bias; float* C;
    __device__ void setz(int e) { bias = b1l + (long)e * FFn; C = Hb + (long)offs[e] * FFn; }
    __device__ void op(int m, int n, float v) { C[(long)m * FFn + n] = fmaxf(v + bias[n], 0.f); }
};
struct EpiMoE2 {  // gate * (acc + b2) scattered to per-(token,slot) buffer
    const float* b2l; const int* offs; const int* perm; const float* gates; float* eout;
    const float* bias; int base;
    __device__ void setz(int e) { bias = b2l + (long)e * Dm; base = offs[e]; }
    __device__ void op(int m, int n, float v) {
        int entry = perm[base + m];
        eout[(long)entry * Dm + n] = gates[entry] * (v + bias[n]);
    }
};

template <class AP, class EP>
__global__ void __launch_bounds__(256) gemm_k(AP ap, const float* __restrict__ B0, long bz,
                                              EP ep, int N, int K)
{
    int z = blockIdx.z;
    int M = ap.setz(z);
    int m0 = blockIdx.x * BM;
    if (m0 >= M) return;
    ep.setz(z);
    const float* Bm = B0 + (long)z * bz;
    int n0 = blockIdx.y * BN;

    __shared__ float As[BM][BK + 1];
    __shared__ __align__(16) float Bs[BK][BN];

    int tid = threadIdx.x;
    int ty = tid >> 4, tx = tid & 15;

    // Hoist A row pointers (fixed across k-steps)
    const float* arow[2];
    int acol[2];
    #pragma unroll
    for (int i = 0; i < 2; i++) {
        int idx = tid * 2 + i;
        int r = idx >> 2, c = idx & 3;
        int gm = m0 + r;
        arow[i] = (gm < M) ? ap.row(gm) : nullptr;
        acol[i] = 4 * c;
    }
    const float* bptr = Bm + (long)(tid >> 4) * N + n0 + 4 * (tid & 15);

    float acc[8][4];
    #pragma unroll
    for (int i = 0; i < 8; i++)
        #pragma unroll
        for (int j = 0; j < 4; j++) acc[i][j] = 0.f;

    for (int k0 = 0; k0 < K; k0 += BK) {
        #pragma unroll
        for (int i = 0; i < 2; i++) {
            int idx = tid * 2 + i;
            int r = idx >> 2;
            float4 v = make_float4(0.f, 0.f, 0.f, 0.f);
            if (arow[i]) v = *(const float4*)(arow[i] + k0 + acol[i]);
            As[r][acol[i] + 0] = v.x; As[r][acol[i] + 1] = v.y;
            As[r][acol[i] + 2] = v.z; As[r][acol[i] + 3] = v.w;
        }
        {
            float4 bv = *(const float4*)(bptr + (long)k0 * N);
            *(float4*)&Bs[tid >> 4][4 * (tid & 15)] = bv;
        }
        __syncthreads();
        #pragma unroll
        for (int k = 0; k < BK; k++) {
            float a[8];
            #pragma unroll
            for (int i = 0; i < 8; i++) a[i] = As[ty * 8 + i][k];
            float4 bv = *(const float4*)&Bs[k][tx * 4];
            float b4[4] = {bv.x, bv.y, bv.z, bv.w};
            #pragma unroll
            for (int i = 0; i < 8; i++)
                #pragma unroll
                for (int j = 0; j < 4; j++) acc[i][j] += a[i] * b4[j];
        }
        __syncthreads();
    }
    #pragma unroll
    for (int i = 0; i < 8; i++) {
        int gm = m0 + ty * 8 + i;
        if (gm < M) {
            #pragma unroll
            for (int j = 0; j < 4; j++) ep.op(gm, n0 + tx * 4 + j, acc[i][j]);
        }
    }
}

// ------------------------- flash attention (fp32, online softmax) -----------
// Block: 64 query rows x full head. KV tiles of 32. 256 threads (16x16).
__global__ void __launch_bounds__(256) flash_k(const float* __restrict__ Q,
                                               const float* __restrict__ Kp,
                                               const float* __restrict__ Vp,
                                               float* __restrict__ O,
                                               const int* __restrict__ am,
                                               int Tk, int causal)
{
    int q0 = blockIdx.x * 64;
    int bh = blockIdx.y;
    int b = bh >> 3, h = bh & 7;
    const float* Qb = Q + (long)b * Tn * Dm + h * DHn;
    const float* Kb = Kp + (long)b * Tk * Dm + h * DHn;
    const float* Vb = Vp + (long)b * Tk * Dm + h * DHn;

    __shared__ float Qs[64][65];
    __shared__ float Ks[32][65];
    __shared__ float Vs[32][65];
    __shared__ float Ps[64][33];
    __shared__ float rowm[64], rowl[64], alph[64];

    int tid = threadIdx.x;
    int ty = tid >> 4, tx = tid & 15;

    #pragma unroll
    for (int it = 0; it < 4; it++) {
        int idx = tid + it * 256;  // float4 units: 64 rows x 16
        int r = idx >> 4, c = idx & 15;
        float4 v = *(const float4*)(Qb + (long)(q0 + r) * Dm + 4 * c);
        Qs[r][4 * c + 0] = v.x; Qs[r][4 * c + 1] = v.y;
        Qs[r][4 * c + 2] = v.z; Qs[r][4 * c + 3] = v.w;
    }
    if (tid < 64) { rowm[tid] = -1e30f; rowl[tid] = 0.f; }

    float o[4][4];
    #pragma unroll
    for (int i = 0; i < 4; i++)
        #pragma unroll
        for (int j = 0; j < 4; j++) o[i][j] = 0.f;

    int kvmax = causal ? (q0 + 64) : Tk;
    for (int kv0 = 0; kv0 < kvmax; kv0 += 32) {
        __syncthreads();
        #pragma unroll
        for (int it = 0; it < 2; it++) {
            int idx = tid + it * 256;  // 32 rows x 16 float4
            int r = idx >> 4, c = idx & 15;
            float4 kv = *(const float4*)(Kb + (long)(kv0 + r) * Dm + 4 * c);
            Ks[r][4 * c + 0] = kv.x; Ks[r][4 * c + 1] = kv.y;
            Ks[r][4 * c + 2] = kv.z; Ks[r][4 * c + 3] = kv.w;
            float4 vv = *(const float4*)(Vb + (long)(kv0 + r) * Dm + 4 * c);
            Vs[r][4 * c + 0] = vv.x; Vs[r][4 * c + 1] = vv.y;
            Vs[r][4 * c + 2] = vv.z; Vs[r][4 * c + 3] = vv.w;
        }
        __syncthreads();

        float s[4][2] = {{0.f, 0.f}, {0.f, 0.f}, {0.f, 0.f}, {0.f, 0.f}};
        #pragma unroll 8
        for (int d = 0; d < 64; d++) {
            float k0v = Ks[2 * tx + 0][d];
            float k1v = Ks[2 * tx + 1][d];
            #pragma unroll
            for (int i = 0; i < 4; i++) {
                float q = Qs[4 * ty + i][d];
                s[i][0] += q * k0v;
                s[i][1] += q * k1v;
            }
        }
        #pragma unroll
        for (int i = 0; i < 4; i++) {
            #pragma unroll
            for (int j = 0; j < 2; j++) {
                float sv = s[i][j] * 0.125f;
                if (causal) {
                    int kg = kv0 + 2 * tx + j;
                    int qg = q0 + 4 * ty + i;
                    if (kg > qg || am[b * Tn + kg] == 0) sv = -1e9f;
                }
                Ps[4 * ty + i][2 * tx + j] = sv;
            }
        }
        __syncthreads();
        if (tid < 64) {
            int r = tid;
            float mo = rowm[r], mx = mo;
            #pragma unroll
            for (int j = 0; j < 32; j++) mx = fmaxf(mx, Ps[r][j]);
            float sum = 0.f;
            #pragma unroll
            for (int j = 0; j < 32; j++) {
                float p = __expf(Ps[r][j] - mx);
                Ps[r][j] = p;
                sum += p;
            }
            float al = __expf(mo - mx);
            rowm[r] = mx;
            rowl[r] = rowl[r] * al + sum;
            alph[r] = al;
        }
        __syncthreads();
        #pragma unroll
        for (int i = 0; i < 4; i++) {
            float al = alph[4 * ty + i];
            #pragma unroll
            for (int j = 0; j < 4; j++) o[i][j] *= al;
        }
        #pragma unroll
        for (int k = 0; k < 32; k++) {
            float vv[4];
            #pragma unroll
            for (int j = 0; j < 4; j++) vv[j] = Vs[k][4 * tx + j];
            #pragma unroll
            for (int i = 0; i < 4; i++) {
                float p = Ps[4 * ty + i][k];
                #pragma unroll
                for (int j = 0; j < 4; j++) o[i][j] += p * vv[j];
            }
        }
    }
    #pragma unroll
    for (int i = 0; i < 4; i++) {
        int qg = q0 + 4 * ty + i;
        float inv = 1.f / rowl[4 * ty + i];
        float* op = O + ((long)b * Tn + qg) * Dm + h * DHn + 4 * tx;
        op[0] = o[i][0] * inv; op[1] = o[i][1] * inv;
        op[2] = o[i][2] * inv; op[3] = o[i][3] * inv;
    }
}

// ------------------------- add + layernorm ----------------------------------
__global__ void __launch_bounds__(256) add_ln_k(const float* __restrict__ base,
                                                const float* __restrict__ delta, int nslots,
                                                const float* __restrict__ g,
                                                const float* __restrict__ bet,
                                                float* __restrict__ out)
{
    int t = blockIdx.x, tid = threadIdx.x;
    __shared__ float red[256];
    float x0 = base[(long)t * Dm + tid];
    float x1 = base[(long)t * Dm + 256 + tid];
    if (nslots == 1) {
        x0 += delta[(long)t * Dm + tid];
        x1 += delta[(long)t * Dm + 256 + tid];
    } else {
        x0 += delta[(long)(t * 2) * Dm + tid] + delta[(long)(t * 2 + 1) * Dm + tid];
        x1 += delta[(long)(t * 2) * Dm + 256 + tid] + delta[(long)(t * 2 + 1) * Dm + 256 + tid];
    }
    red[tid] = x0 + x1;
    __syncthreads();
    #pragma unroll
    for (int s = 128; s > 0; s >>= 1) {
        if (tid < s) red[tid] += red[tid + s];
        __syncthreads();
    }
    float mu = red[0] * (1.f / Dm);
    __syncthreads();
    float d0 = x0 - mu, d1 = x1 - mu;
    red[tid] = d0 * d0 + d1 * d1;
    __syncthreads();
    #pragma unroll
    for (int s = 128; s > 0; s >>= 1) {
        if (tid < s) red[tid] += red[tid + s];
        __syncthreads();
    }
    float rs = rsqrtf(red[0] * (1.f / Dm) + 1e-5f);
    out[(long)t * Dm + tid] = d0 * rs * g[tid] + bet[tid];
    out[(long)t * Dm + 256 + tid] = d1 * rs * g[tid + 256] + bet[tid + 256];
}

// ------------------------- router: softmax + top2 ---------------------------
__global__ void __launch_bounds__(256) router_k(const float* __restrict__ y,
                                                const float* __restrict__ rw,
                                                const float* __restrict__ rb,
                                                float* __restrict__ probs,
                                                int* __restrict__ topi,
                                                float* __restrict__ gates)
{
    int warp = (blockIdx.x * blockDim.x + threadIdx.x) >> 5;
    int lane = threadIdx.x & 31;
    if (warp >= NT) return;
    const float* x = y + (long)warp * Dm;
    float acc[En];
    #pragma unroll
    for (int e = 0; e < En; e++) acc[e] = 0.f;
    for (int d = lane; d < Dm; d += 32) {
        float xv = x[d];
        const float* w = rw + (long)d * En;
        #pragma unroll
        for (int e = 0; e < En; e++) acc[e] += xv * w[e];
    }
    #pragma unroll
    for (int e = 0; e < En; e++) {
        #pragma unroll
        for (int off = 16; off > 0; off >>= 1)
            acc[e] += __shfl_xor_sync(0xffffffffu, acc[e], off);
    }
    float lg[En], p[En];
    float m = -1e30f;
    #pragma unroll
    for (int e = 0; e < En; e++) { lg[e] = acc[e] + rb[e]; m = fmaxf(m, lg[e]); }
    float sum = 0.f;
    #pragma unroll
    for (int e = 0; e < En; e++) { p[e] = __expf(lg[e] - m); sum += p[e]; }
    float inv = 1.f / sum;
    #pragma unroll
    for (int e = 0; e < En; e++) p[e] *= inv;
    int e0 = 0; float v0 = p[0];
    #pragma unroll
    for (int e = 1; e < En; e++) if (p[e] > v0) { v0 = p[e]; e0 = e; }
    int e1 = -1; float v1 = -1.f;
    #pragma unroll
    for (int e = 0; e < En; e++) if (e != e0 && p[e] > v1) { v1 = p[e]; e1 = e; }
    if (lane == 0) {
        #pragma unroll
        for (int e = 0; e < En; e++) probs[(long)warp * En + e] = p[e];
        float den = 1.f / (v0 + v1);
        topi[warp * 2 + 0] = e0;
        topi[warp * 2 + 1] = e1;
        gates[warp * 2 + 0] = v0 * den;
        gates[warp * 2 + 1] = v1 * den;
    }
}

// ------------------------- aux loss (deterministic reduction) ---------------
__global__ void __launch_bounds__(256) lb_k(const float* __restrict__ probs,
                                            const int* __restrict__ topi,
                                            float* __restrict__ lbout, int first)
{
    __shared__ float sm[256];
    int tid = threadIdx.x;
    float ps[En], cs[En];
    #pragma unroll
    for (int e = 0; e < En; e++) { ps[e] = 0.f; cs[e] = 0.f; }
    for (int t = tid; t < NT; t += 256) {
        #pragma unroll
        for (int e = 0; e < En; e++) ps[e] += probs[(long)t * En + e];
        int a = topi[2 * t], b = topi[2 * t + 1];
        #pragma unroll
        for (int e = 0; e < En; e++) cs[e] += (float)((e == a) + (e == b));
    }
    float lb = 0.f;
    for (int e = 0; e < En; e++) {
        sm[tid] = ps[e]; __syncthreads();
        for (int s = 128; s > 0; s >>= 1) { if (tid < s) sm[tid] += sm[tid + s]; __syncthreads(); }
        float P = sm[0]; __syncthreads();
        sm[tid] = cs[e]; __syncthreads();
        for (int s = 128; s > 0; s >>= 1) { if (tid < s) sm[tid] += sm[tid + s]; __syncthreads(); }
        float C = sm[0]; __syncthreads();
        lb += (C * (1.f / NT)) * (P * (1.f / NT));
    }
    if (tid == 0) {
        lb *= (float)En;
        if (first) *lbout = lb; else *lbout += lb;
    }
}

// ------------------------- token grouping by expert (deterministic) ---------
__global__ void __launch_bounds__(256) group_k(const int* __restrict__ topi,
                                               int* __restrict__ perm,
                                               int* __restrict__ offsets)
{
    __shared__ int cnts[En];
    __shared__ int offs_s[En + 1];
    int w = threadIdx.x >> 5, lane = threadIdx.x & 31;
    int c = 0;
    for (int i = lane; i < NEn; i += 32) c += (topi[i] == w);
    #pragma unroll
    for (int off = 16; off > 0; off >>= 1) c += __shfl_xor_sync(0xffffffffu, c, off);
    if (lane == 0) cnts[w] = c;
    __syncthreads();
    if (threadIdx.x == 0) {
        offs_s[0] = 0;
        for (int e = 0; e < En; e++) offs_s[e + 1] = offs_s[e] + cnts[e];
        for (int e = 0; e <= En; e++) offsets[e] = offs_s[e];
    }
    __syncthreads();
    int pos = offs_s[w];
    for (int i0 = 0; i0 < NEn; i0 += 32) {
        int i = i0 + lane;
        int e = topi[i];
        unsigned mk = __ballot_sync(0xffffffffu, e == w);
        if (e == w) {
            int r = __popc(mk & ((1u << lane) - 1u));
            perm[pos + r] = i;
        }
        pos += __popc(mk);
    }
}

// ------------------------- host orchestration -------------------------------
extern "C" void kernel_launch(void* const* d_in, const int* in_sizes, int n_in,
                              void* d_out, int out_size)
{
    (void)in_sizes; (void)n_in;
    const int*   ids  = (const int*)d_in[0];
    const float* enc  = (const float*)d_in[1];
    const int*   am   = (const int*)d_in[2];
    const float* emb  = (const float*)d_in[3];
    const float* pos  = (const float*)d_in[4];
    const float* sa_w = (const float*)d_in[5];
    const float* sa_b = (const float*)d_in[6];
    const float* ca_w = (const float*)d_in[7];
    const float* ca_b = (const float*)d_in[8];
    const float* ln_g = (const float*)d_in[9];
    const float* ln_b = (const float*)d_in[10];
    const float* rw   = (const float*)d_in[11];
    const float* rb   = (const float*)d_in[12];
    const float* w1   = (const float*)d_in[13];
    const float* b1   = (const float*)d_in[14];
    const float* w2   = (const float*)d_in[15];
    const float* b2   = (const float*)d_in[16];
    float* out = (float*)d_out;

    float *y, *qkv, *attn, *proj, *probs, *gates, *H, *eout;
    int *topi, *perm, *offs;
    cudaGetSymbolAddress((void**)&y, g_y);
    cudaGetSymbolAddress((void**)&qkv, g_qkv);
    cudaGetSymbolAddress((void**)&attn, g_attn);
    cudaGetSymbolAddress((void**)&proj, g_proj);
    cudaGetSymbolAddress((void**)&probs, g_probs);
    cudaGetSymbolAddress((void**)&gates, g_gates);
    cudaGetSymbolAddress((void**)&H, g_H);
    cudaGetSymbolAddress((void**)&eout, g_eout);
    cudaGetSymbolAddress((void**)&topi, g_topi);
    cudaGetSymbolAddress((void**)&perm, g_perm);
    cudaGetSymbolAddress((void**)&offs, g_offs);

    const long DD = (long)Dm * Dm;
    const long SLOT = (long)NT * Dm;

    embed_k<<<NT, 256>>>(ids, emb, pos, y);

    for (int l = 0; l < Ln; l++) {
        // ---- self attention ----
        gemm_k<<<dim3(NT / BM, Dm / BN, 3), 256>>>(
            RowA{y, Dm, 0, NT}, sa_w + l * 4 * DD, DD,
            EpiBias<false>{sa_b + (long)l * 4 * Dm, Dm, qkv, SLOT, Dm}, Dm, Dm);
        flash_k<<<dim3(Tn / 64, 16), 256>>>(qkv, qkv + SLOT, qkv + 2 * SLOT, attn, am, Tn, 1);
        gemm_k<<<dim3(NT / BM, Dm / BN, 1), 256>>>(
            RowA{attn, Dm, 0, NT}, sa_w + l * 4 * DD + 3 * DD, 0,
            EpiBias<false>{sa_b + (long)l * 4 * Dm + 3 * Dm, 0, proj, 0, Dm}, Dm, Dm);
        add_ln_k<<<NT, 256>>>(y, proj, 1, ln_g + (l * 3 + 0) * Dm, ln_b + (l * 3 + 0) * Dm, y);

        // ---- cross attention ----
        gemm_k<<<dim3(NT / BM, Dm / BN, 1), 256>>>(
            RowA{y, Dm, 0, NT}, ca_w + l * 4 * DD, 0,
            EpiBias<false>{ca_b + (long)l * 4 * Dm, 0, qkv, 0, Dm}, Dm, Dm);
        gemm_k<<<dim3(NT / BM, Dm / BN, 2), 256>>>(
            RowA{enc, Dm, 0, NT}, ca_w + l * 4 * DD + DD, DD,
            EpiBias<false>{ca_b + (long)l * 4 * Dm + Dm, Dm, qkv + SLOT, SLOT, Dm}, Dm, Dm);
        flash_k<<<dim3(Tn / 64, 16), 256>>>(qkv, qkv + SLOT, qkv + 2 * SLOT, attn, nullptr, Tn, 0);
        gemm_k<<<dim3(NT / BM, Dm / BN, 1), 256>>>(
            RowA{attn, Dm, 0, NT}, ca_w + l * 4 * DD + 3 * DD, 0,
            EpiBias<false>{ca_b + (long)l * 4 * Dm + 3 * Dm, 0, proj, 0, Dm}, Dm, Dm);
        add_ln_k<<<NT, 256>>>(y, proj, 1, ln_g + (l * 3 + 1) * Dm, ln_b + (l * 3 + 1) * Dm, y);

        // ---- sparse MoE ----
        router_k<<<NT / 8, 256>>>(y, rw + (long)l * Dm * En, rb + l * En, probs, topi, gates);
        lb_k<<<1, 256>>>(probs, topi, out + (out_size - 1), l == 0 ? 1 : 0);
        group_k<<<1, 256>>>(topi, perm, offs);
        gemm_k<<<dim3(NEn / BM, FFn / BN, En), 256>>>(
            GatherA{y, perm, offs, 0}, w1 + (long)l * En * Dm * FFn, (long)Dm * FFn,
            EpiMoE1{b1 + (long)l * En * FFn, offs, H, nullptr, nullptr}, FFn, Dm);
        gemm_k<<<dim3(NEn / BM, Dm / BN, En), 256>>>(
            HRowA{H, offs, nullptr}, w2 + (long)l * En * FFn * Dm, (long)FFn * Dm,
            EpiMoE2{b2 + (long)l * En * Dm, offs, perm, gates, eout, nullptr, 0}, Dm, FFn);
        float* lnout = (l == Ln - 1) ? out : y;
        add_ln_k<<<NT, 256>>>(y, eout, 2, ln_g + (l * 3 + 2) * Dm, ln_b + (l * 3 + 2) * Dm, lnout);
    }
}